// round 15
// baseline (speedup 1.0000x reference)
#include <cuda_runtime.h>
#include <cuda_fp16.h>
#include <cstdint>

// Problem constants
#define Bc   4
#define Tc   2048
#define Dc   1024
#define Hc   16
#define DHc  64
#define T2c  1024
#define LN_EPS 1e-5f

#define MBIG (Bc * Tc)      // 8192
#define MSML (Bc * T2c)     // 4096
#define NT   (Dc / 2)       // 512

#define NCHK 128            // chunks per (b,h), 16 rows each

// ---------------- scratch (device globals) ----------------
// v is HEAD-MAJOR: [b][h][t][d]
__device__ __half g_vh[MBIG * Dc];        // 16 MB
__device__ float  g_wq[Hc * Dc];
__device__ float  g_w[Bc * Hc * Tc];      // w = exp(score) (no max; |s|<<1)
__device__ float  g_csumN[64 * NCHK * DHc];   // 2 MB chunk sums -> prefixes (in place)
__device__ float  g_csumZ[64 * NCHK];
__device__ float  g_cprefZ[64 * NCHK];
__device__ int    g_ctr[Bc * 4];          // last-block counters (zero-init; reset each run)
__device__ __half g_xhi[MBIG * Dc];       // 16 MB
__device__ __half g_wvhi[Dc * Dc];        // transposed [N][K]
__device__ __half g_wthi[NT * Dc];        // transposed [N][K]
__device__ __half g_pnhi[MSML * Dc];

// ---------------- 1. prep: wq + transpose/convert Wv, Wt --------------------
__global__ __launch_bounds__(256) void prep_kernel(
    const float* __restrict__ Wk, const float* __restrict__ q,
    const float* __restrict__ Wv, const float* __restrict__ Wt)
{
    __shared__ float tile[32][33];
    int bid = blockIdx.x, tid = threadIdx.x;
    if (bid < 64) {
        int idx = bid * 256 + tid;
        int d = idx >> 4, h = idx & 15;
        const float* wrow = Wk + (size_t)d * Dc + h * DHc;
        const float* qrow = q + h * DHc;
        float s = 0.f;
#pragma unroll
        for (int i = 0; i < DHc; i++) s = fmaf(wrow[i], qrow[i], s);
        g_wq[h * Dc + d] = s;
        return;
    }
    const float* W; __half* outT; int K, N, bx, by;
    if (bid < 64 + 1024) {
        int t = bid - 64;
        W = Wv; outT = g_wvhi; K = Dc; N = Dc; bx = t & 31; by = t >> 5;
    } else {
        int t = bid - 1088;
        W = Wt; outT = g_wthi; K = Dc; N = NT; bx = t & 15; by = t >> 4;
    }
    int tx = tid & 31, ty = tid >> 5;
    int bn = bx * 32, bk = by * 32;
#pragma unroll
    for (int j = 0; j < 4; j++)
        tile[ty + j * 8][tx] = W[(size_t)(bk + ty + j * 8) * N + bn + tx];
    __syncthreads();
#pragma unroll
    for (int j = 0; j < 4; j++) {
        int n = bn + ty + j * 8;
        int k = bk + tx;
        outT[(size_t)n * K + k] = __float2half_rn(tile[tx][ty + j * 8]);
    }
}

// ---------------- 2. scores (w = exp(s/8)) + x->fp16 ------------------------
__global__ __launch_bounds__(512) void scores_kernel(const float* __restrict__ x) {
    extern __shared__ float swq[];              // 16384 floats
    int tid = threadIdx.x;
    float4* swq4 = (float4*)swq;
    const float4* gwq4 = (const float4*)g_wq;
#pragma unroll
    for (int k = 0; k < 8; k++) swq4[tid + k * 512] = gwq4[tid + k * 512];

    int wid = tid >> 5, lane = tid & 31;
    int row = blockIdx.x * 16 + wid;
    const float4* xr4 = (const float4*)(x + (size_t)row * Dc);
    __half2* hp = (__half2*)(g_xhi + (size_t)row * Dc);
    float4 xv[8];
#pragma unroll
    for (int j = 0; j < 8; j++) {
        float4 v = xr4[lane + j * 32];
        xv[j] = v;
        hp[(lane + j * 32) * 2]     = __floats2half2_rn(v.x, v.y);
        hp[(lane + j * 32) * 2 + 1] = __floats2half2_rn(v.z, v.w);
    }
    __syncthreads();
    int b = row >> 11, t = row & (Tc - 1);
#pragma unroll
    for (int h = 0; h < 16; h++) {
        float s = 0.f;
#pragma unroll
        for (int j = 0; j < 8; j++) {
            float4 wv = swq4[h * 256 + lane + j * 32];
            s += xv[j].x * wv.x + xv[j].y * wv.y + xv[j].z * wv.z + xv[j].w * wv.w;
        }
#pragma unroll
        for (int o = 16; o; o >>= 1) s += __shfl_xor_sync(0xffffffffu, s, o);
        if (lane == 0) g_w[(b * Hc + h) * Tc + t] = expf(s * 0.125f);
    }
}

// ---------------- 3a. v-GEMM 128x256 (head-major) + chunk sums + inline scan
#define LD2 40
#define ASLAB (128 * LD2)               // halfs
#define BSLAB (256 * LD2)
#define STAGE (ASLAB + BSLAB)           // 15360 halfs
#define VG_SMEM (3 * STAGE * 2)         // 92160 B

__device__ __forceinline__ void mma16816(float* d, const uint32_t* a, const uint32_t* b) {
    asm volatile(
        "mma.sync.aligned.m16n8k16.row.col.f32.f16.f16.f32 "
        "{%0,%1,%2,%3}, {%4,%5,%6,%7}, {%8,%9}, {%0,%1,%2,%3};\n"
        : "+f"(d[0]), "+f"(d[1]), "+f"(d[2]), "+f"(d[3])
        : "r"(a[0]), "r"(a[1]), "r"(a[2]), "r"(a[3]), "r"(b[0]), "r"(b[1]));
}

__device__ __forceinline__ void cp_async16(uint32_t smem_addr, const void* gptr) {
    asm volatile("cp.async.cg.shared.global [%0], [%1], 16;\n"
                 :: "r"(smem_addr), "l"(gptr));
}

__global__ __launch_bounds__(256, 1) void vgemm_kernel(
    const __half* __restrict__ A, const __half* __restrict__ B,
    __half* __restrict__ C, int M, int N, int K)
{
    extern __shared__ __align__(16) __half smh[];
    int tid = threadIdx.x;
    int bm = blockIdx.y * 128, bn = blockIdx.x * 256;
    uint32_t sBase = (uint32_t)__cvta_generic_to_shared(smh);
    const int NS = K >> 5;

#define VLOAD_SLAB(slab, buf)                                                  \
    do {                                                                       \
        int k0_ = (slab) << 5;                                                 \
        uint32_t st_ = sBase + (uint32_t)(buf) * (STAGE * 2);                  \
        _Pragma("unroll")                                                      \
        for (int i_ = 0; i_ < 2; i_++) {                                       \
            int idx_ = tid + i_ * 256;                                         \
            int row_ = idx_ >> 2, part_ = idx_ & 3;                            \
            cp_async16(st_ + (uint32_t)((row_ * LD2 + part_ * 8) * 2),         \
                       A + (size_t)(bm + row_) * K + k0_ + part_ * 8);         \
        }                                                                      \
        _Pragma("unroll")                                                      \
        for (int i_ = 0; i_ < 4; i_++) {                                       \
            int idx_ = tid + i_ * 256;                                         \
            int row_ = idx_ >> 2, part_ = idx_ & 3;                            \
            cp_async16(st_ + (uint32_t)(ASLAB * 2 + (row_ * LD2 + part_ * 8) * 2), \
                       B + (size_t)(bn + row_) * K + k0_ + part_ * 8);         \
        }                                                                      \
        asm volatile("cp.async.commit_group;");                                \
    } while (0)

    int lane = tid & 31, wid = tid >> 5;
    int wm = wid & 1, wn = wid >> 1;
    int grp = lane >> 2, qid = lane & 3;

    float acc[4][8][4];
#pragma unroll
    for (int i = 0; i < 4; i++)
#pragma unroll
        for (int j = 0; j < 8; j++)
#pragma unroll
            for (int l = 0; l < 4; l++) acc[i][j][l] = 0.f;

    VLOAD_SLAB(0, 0);
    VLOAD_SLAB(1, 1);
    VLOAD_SLAB(2, 2);

    int buf = 0;
    for (int i = 0; i < NS; i++) {
        int rem = NS - 1 - i;
        if (rem >= 2)      asm volatile("cp.async.wait_group 2;");
        else if (rem == 1) asm volatile("cp.async.wait_group 1;");
        else               asm volatile("cp.async.wait_group 0;");
        __syncthreads();

        const __half* cA = smh + buf * STAGE;
        const __half* cB = smh + buf * STAGE + ASLAB;
#pragma unroll
        for (int ks = 0; ks < 2; ks++) {
            uint32_t ah[4][4], bh[8][2];
#pragma unroll
            for (int mt = 0; mt < 4; mt++) {
                int r = wm * 64 + mt * 16 + grp;
                ah[mt][0] = *(const uint32_t*)&cA[r * LD2 + ks * 16 + qid * 2];
                ah[mt][1] = *(const uint32_t*)&cA[(r + 8) * LD2 + ks * 16 + qid * 2];
                ah[mt][2] = *(const uint32_t*)&cA[r * LD2 + ks * 16 + qid * 2 + 8];
                ah[mt][3] = *(const uint32_t*)&cA[(r + 8) * LD2 + ks * 16 + qid * 2 + 8];
            }
#pragma unroll
            for (int nt = 0; nt < 8; nt++) {
                int n = wn * 64 + nt * 8 + grp;
                bh[nt][0] = *(const uint32_t*)&cB[n * LD2 + ks * 16 + qid * 2];
                bh[nt][1] = *(const uint32_t*)&cB[n * LD2 + ks * 16 + qid * 2 + 8];
            }
#pragma unroll
            for (int mt = 0; mt < 4; mt++)
#pragma unroll
                for (int nt = 0; nt < 8; nt++)
                    mma16816(acc[mt][nt], ah[mt], bh[nt]);
        }
        __syncthreads();
        if (i + 3 < NS) VLOAD_SLAB(i + 3, buf);
        buf = (buf == 2) ? 0 : buf + 1;
    }

    // store v (fp16, HEAD-MAJOR: [b][h][t][d])
    {
        int b = bm >> 11, tbase = bm & (Tc - 1);
        int h = (bn >> 6) + wn;
        __half* vbase = C + ((size_t)(b * Hc + h) * Tc + tbase) * DHc;
#pragma unroll
        for (int nt = 0; nt < 8; nt++) {
            int d = nt * 8 + qid * 2;
#pragma unroll
            for (int mt = 0; mt < 4; mt++) {
                int t = wm * 64 + mt * 16 + grp;
                *(__half2*)&vbase[(size_t)t * DHc + d] =
                    __floats2half2_rn(acc[mt][nt][0], acc[mt][nt][1]);
                *(__half2*)&vbase[(size_t)(t + 8) * DHc + d] =
                    __floats2half2_rn(acc[mt][nt][2], acc[mt][nt][3]);
            }
        }
    }

    // fused pass1: per-16-row-chunk sums of w*v (+ chunk Z) from fp32 accs
    __syncthreads();
    float* swe = (float*)smh;           // 512 floats, reuse smem
    int b = bm >> 11, tbase = bm & (Tc - 1);
#pragma unroll
    for (int i = 0; i < 2; i++) {
        int idx = tid + i * 256;
        int hh = idx >> 7, r = idx & 127;
        swe[idx] = g_w[(size_t)((b * Hc + (bn >> 6) + hh) * Tc) + tbase + r];
    }
    __syncthreads();
    {
        int bh = b * Hc + (bn >> 6) + wn;
        const float* swp = swe + wn * 128 + wm * 64;
        int cbase = (tbase >> 4) + wm * 4;
#pragma unroll
        for (int mt = 0; mt < 4; mt++) {
            float w0 = swp[mt * 16 + grp];
            float w8 = swp[mt * 16 + grp + 8];
            int c = cbase + mt;
            float z = w0 + w8;
#pragma unroll
            for (int o = 16; o >= 4; o >>= 1) z += __shfl_xor_sync(0xffffffffu, z, o);
            if (lane == 0) g_csumZ[bh * NCHK + c] = z;
#pragma unroll
            for (int nt = 0; nt < 8; nt++) {
                float s0 = w0 * acc[mt][nt][0] + w8 * acc[mt][nt][2];
                float s1 = w0 * acc[mt][nt][1] + w8 * acc[mt][nt][3];
#pragma unroll
                for (int o = 16; o >= 4; o >>= 1) {
                    s0 += __shfl_xor_sync(0xffffffffu, s0, o);
                    s1 += __shfl_xor_sync(0xffffffffu, s1, o);
                }
                if (grp == 0) {
                    int ix = (bh * NCHK + c) * DHc + nt * 8 + qid * 2;
                    g_csumN[ix] = s0;
                    g_csumN[ix + 1] = s1;
                }
            }
        }
    }

    // ---- inline scan: last block of each (b, bn-group) scans 4 bh in place --
    __shared__ int sOld;
    __threadfence();
    if (tid == 0) sOld = atomicAdd(&g_ctr[b * 4 + (bn >> 8)], 1);
    __syncthreads();
    if (sOld == 15) {
        __threadfence();                 // acquire: see all 16 blocks' sums
        int bhl = tid >> 6, d = tid & 63;
        int bh = b * Hc + (bn >> 6) + bhl;
        float* basep = g_csumN + (size_t)bh * NCHK * DHc + d;
        float run = 0.f;
#pragma unroll 4
        for (int c = 0; c < NCHK; c++) {
            float tv = basep[(size_t)c * DHc];
            basep[(size_t)c * DHc] = run;
            run += tv;
        }
        if (d == 0) {
            const float* zb = g_csumZ + bh * NCHK;
            float* zp = g_cprefZ + bh * NCHK;
            float rz = 0.f;
#pragma unroll 4
            for (int c = 0; c < NCHK; c++) {
                float tv = zb[c];
                zp[c] = rz;
                rz += tv;
            }
        }
        __syncthreads();
        if (tid == 0) g_ctr[b * 4 + (bn >> 8)] = 0;   // reset for next replay
    }
#undef VLOAD_SLAB
}

// ---------------- 3b. theta-GEMM: 128x128 tile, BK=32, 3-stage --------------
#define TSLAB (128 * LD2)
#define TSLAB_B (TSLAB * 2)
#define TG_SMEM (6 * TSLAB_B)           // 61440 B

__global__ __launch_bounds__(256, 1) void tgemm_kernel(
    const __half* __restrict__ A, const __half* __restrict__ B,
    const float* __restrict__ bias, float* __restrict__ C,
    int M, int N, int K)
{
    extern __shared__ __align__(16) __half smh[];
    __half* sA = smh;
    __half* sB = smh + 3 * TSLAB;
    int tid = threadIdx.x;
    int bm = blockIdx.y * 128, bn = blockIdx.x * 128;
    uint32_t aBase = (uint32_t)__cvta_generic_to_shared(sA);
    uint32_t bBase = (uint32_t)__cvta_generic_to_shared(sB);
    const int NS = K >> 5;

#define TLOAD_SLAB(slab, buf)                                                  \
    do {                                                                       \
        int k0_ = (slab) << 5;                                                 \
        _Pragma("unroll")                                                      \
        for (int i_ = 0; i_ < 2; i_++) {                                       \
            int idx_ = tid + i_ * 256;                                         \
            int row_ = idx_ >> 2, part_ = idx_ & 3;                            \
            uint32_t so_ = (uint32_t)((buf) * TSLAB_B + (row_ * LD2 + part_ * 8) * 2); \
            cp_async16(aBase + so_, A + (size_t)(bm + row_) * K + k0_ + part_ * 8);   \
            cp_async16(bBase + so_, B + (size_t)(bn + row_) * K + k0_ + part_ * 8);   \
        }                                                                      \
        asm volatile("cp.async.commit_group;");                                \
    } while (0)

    int lane = tid & 31, wid = tid >> 5;
    int wm = wid & 1, wn = wid >> 1;
    int grp = lane >> 2, qid = lane & 3;

    float acc[4][4][4];
#pragma unroll
    for (int i = 0; i < 4; i++)
#pragma unroll
        for (int j = 0; j < 4; j++)
#pragma unroll
            for (int l = 0; l < 4; l++) acc[i][j][l] = 0.f;

    TLOAD_SLAB(0, 0);
    if (NS > 1) TLOAD_SLAB(1, 1);
    if (NS > 2) TLOAD_SLAB(2, 2);

    int buf = 0;
    for (int i = 0; i < NS; i++) {
        int rem = NS - 1 - i;
        if (rem >= 2)      asm volatile("cp.async.wait_group 2;");
        else if (rem == 1) asm volatile("cp.async.wait_group 1;");
        else               asm volatile("cp.async.wait_group 0;");
        __syncthreads();

        const __half* cA = sA + buf * TSLAB;
        const __half* cB = sB + buf * TSLAB;
#pragma unroll
        for (int ks = 0; ks < 2; ks++) {
            uint32_t ah[4][4], bh[4][2];
#pragma unroll
            for (int mt = 0; mt < 4; mt++) {
                int r = wm * 64 + mt * 16 + grp;
                ah[mt][0] = *(const uint32_t*)&cA[r * LD2 + ks * 16 + qid * 2];
                ah[mt][1] = *(const uint32_t*)&cA[(r + 8) * LD2 + ks * 16 + qid * 2];
                ah[mt][2] = *(const uint32_t*)&cA[r * LD2 + ks * 16 + qid * 2 + 8];
                ah[mt][3] = *(const uint32_t*)&cA[(r + 8) * LD2 + ks * 16 + qid * 2 + 8];
            }
#pragma unroll
            for (int nt = 0; nt < 4; nt++) {
                int n = wn * 32 + nt * 8 + grp;
                bh[nt][0] = *(const uint32_t*)&cB[n * LD2 + ks * 16 + qid * 2];
                bh[nt][1] = *(const uint32_t*)&cB[n * LD2 + ks * 16 + qid * 2 + 8];
            }
#pragma unroll
            for (int mt = 0; mt < 4; mt++)
#pragma unroll
                for (int nt = 0; nt < 4; nt++)
                    mma16816(acc[mt][nt], ah[mt], bh[nt]);
        }
        __syncthreads();
        if (i + 3 < NS) TLOAD_SLAB(i + 3, buf);
        buf = (buf == 2) ? 0 : buf + 1;
    }

#pragma unroll
    for (int nt = 0; nt < 4; nt++) {
        int c0 = bn + wn * 32 + nt * 8 + qid * 2;
        float b0 = bias[c0], b1 = bias[c0 + 1];
#pragma unroll
        for (int mt = 0; mt < 4; mt++) {
            int r = bm + wm * 64 + mt * 16 + grp;
            *(float2*)&C[(size_t)r * N + c0] =
                make_float2(acc[mt][nt][0] + b0, acc[mt][nt][1] + b1);
            *(float2*)&C[(size_t)(r + 8) * N + c0] =
                make_float2(acc[mt][nt][2] + b0, acc[mt][nt][3] + b1);
        }
    }
#undef TLOAD_SLAB
}

// ---------------- 4. poolln: replay + LayerNorm + mag (fused) ---------------
// grid 512 = (b, jg): jg = 16-row chunk index (128 per b), 8 output rows each.
// block 512 (16 warps): warp h replays head h; then warps 0..7 do LN rows.
__global__ __launch_bounds__(512) void poolln_kernel(
    const float* __restrict__ lng, const float* __restrict__ lnb,
    const float* __restrict__ Wm, const float* __restrict__ bm,
    float* __restrict__ mag_out)
{
    __shared__ float sw[Hc * 16];           // 1 KB
    __shared__ float sPN[Hc * DHc];         // 4 KB prefix N
    __shared__ float sPZ[Hc];
    __shared__ __half sPool[8 * Dc];        // 16 KB pooled tile [j_local][d]
    int blk = blockIdx.x;
    int b = blk >> 7, jg = blk & 127;
    int tid = threadIdx.x, wid = tid >> 5, lane = tid & 31;
    int t0 = jg * 16;

    if (tid < Hc * 16) {
        int h = tid >> 4, i = tid & 15;
        sw[tid] = g_w[(b * Hc + h) * Tc + t0 + i];
    }
#pragma unroll
    for (int k = 0; k < 2; k++) {
        int s = tid + k * 512;              // s = h*64 + d
        int h = s >> 6, d = s & 63;
        sPN[s] = g_csumN[((size_t)(b * Hc + h) * NCHK + jg) * DHc + d];
    }
    if (tid < Hc) sPZ[tid] = g_cprefZ[(b * Hc + tid) * NCHK + jg];
    __syncthreads();

    // replay: warp = head; contiguous 2 KB v stream
    {
        int h = wid;
        const __half2* vp = (const __half2*)(g_vh +
            ((size_t)(b * Hc + h) * Tc + t0) * DHc) + lane;
        float2 accN = make_float2(sPN[h * 64 + 2 * lane], sPN[h * 64 + 2 * lane + 1]);
        float accZ = sPZ[h];
        __half2* pool = (__half2*)sPool + h * 32 + lane;   // row stride 512 half2
#pragma unroll
        for (int i = 0; i < 16; i += 2) {
            float w0 = sw[h * 16 + i];
            float2 f0 = __half22float2(vp[i * 32]);
            accN.x = fmaf(w0, f0.x, accN.x);
            accN.y = fmaf(w0, f0.y, accN.y);
            accZ += w0;
            float inv = __fdividef(1.f, accZ);
            pool[(i >> 1) * 512] = __floats2half2_rn(accN.x * inv, accN.y * inv);
            float w1 = sw[h * 16 + i + 1];
            float2 f1 = __half22float2(vp[(i + 1) * 32]);
            accN.x = fmaf(w1, f1.x, accN.x);
            accN.y = fmaf(w1, f1.y, accN.y);
            accZ += w1;
        }
    }
    __syncthreads();

    // LN + mag: warps 0..7, warp r = output row j = jg*8 + r
    if (wid < 8) {
        int r = wid;
        const __half2* row = (const __half2*)sPool + r * 512 + lane;
        float2 vals[16];
        float s = 0.f;
#pragma unroll
        for (int k = 0; k < 16; k++) {
            vals[k] = __half22float2(row[k * 32]);
            s += vals[k].x + vals[k].y;
        }
#pragma unroll
        for (int o = 16; o; o >>= 1) s += __shfl_xor_sync(0xffffffffu, s, o);
        float mu = s * (1.f / Dc);
        float sq = 0.f;
#pragma unroll
        for (int k = 0; k < 16; k++) {
            vals[k].x -= mu; vals[k].y -= mu;
            sq += vals[k].x * vals[k].x + vals[k].y * vals[k].y;
        }
#pragma unroll
        for (int o = 16; o; o >>= 1) sq += __shfl_xor_sync(0xffffffffu, sq, o);
        float rstd = rsqrtf(sq * (1.f / Dc) + LN_EPS);

        int rowidx = b * T2c + jg * 8 + r;
        __half2* hp = (__half2*)(g_pnhi + (size_t)rowidx * Dc);
        float dot = 0.f;
#pragma unroll
        for (int k = 0; k < 16; k++) {
            int d2 = lane + k * 32;
            float2 g2 = ((const float2*)lng)[d2];
            float2 b2 = ((const float2*)lnb)[d2];
            float yx = vals[k].x * rstd * g2.x + b2.x;
            float yy = vals[k].y * rstd * g2.y + b2.y;
            hp[d2] = __floats2half2_rn(yx, yy);
            float2 wm2 = ((const float2*)Wm)[d2];
            dot += yx * wm2.x + yy * wm2.y;
        }
#pragma unroll
        for (int o = 16; o; o >>= 1) dot += __shfl_xor_sync(0xffffffffu, dot, o);
        if (lane == 0) mag_out[rowidx] = 1.f / (1.f + expf(-(dot + bm[0])));
    }
}

// ---------------- launch ----------------
extern "C" void kernel_launch(void* const* d_in, const int* in_sizes, int n_in,
                              void* d_out, int out_size) {
    const float* x   = (const float*)d_in[0];
    const float* qy  = (const float*)d_in[1];
    const float* Wk  = (const float*)d_in[2];
    const float* Wv  = (const float*)d_in[3];
    const float* Wt  = (const float*)d_in[4];
    const float* bt  = (const float*)d_in[5];
    const float* Wm  = (const float*)d_in[6];
    const float* bm  = (const float*)d_in[7];
    const float* lng = (const float*)d_in[8];
    const float* lnb = (const float*)d_in[9];
    float* out = (float*)d_out;

    __half *pvh, *pxhi, *pwvhi, *pwthi, *ppnhi;
    cudaGetSymbolAddress((void**)&pvh, g_vh);
    cudaGetSymbolAddress((void**)&pxhi, g_xhi);
    cudaGetSymbolAddress((void**)&pwvhi, g_wvhi);
    cudaGetSymbolAddress((void**)&pwthi, g_wthi);
    cudaGetSymbolAddress((void**)&ppnhi, g_pnhi);

    cudaFuncSetAttribute(scores_kernel,
                         cudaFuncAttributeMaxDynamicSharedMemorySize, 65536);
    cudaFuncSetAttribute(vgemm_kernel,
                         cudaFuncAttributeMaxDynamicSharedMemorySize, VG_SMEM);
    cudaFuncSetAttribute(tgemm_kernel,
                         cudaFuncAttributeMaxDynamicSharedMemorySize, TG_SMEM);

    // 1. weight prep (wq + WvT + WtT)
    prep_kernel<<<1600, 256>>>(Wk, qy, Wv, Wt);

    // 2. w = exp(scores), x -> fp16
    scores_kernel<<<MBIG / 16, 512, 65536>>>(x);

    // 3. v = x @ Wv (fp16, head-major) + chunk sums + inline last-block scan
    {
        dim3 grid(Dc / 256, MBIG / 128);
        vgemm_kernel<<<grid, 256, VG_SMEM>>>(pxhi, pwvhi, pvh, MBIG, Dc, Dc);
    }

    // 4. poolln: replay + LN + mag -> pnhi + mag (fused)
    poolln_kernel<<<512, 512>>>(lng, lnb, Wm, bm, out + (size_t)MSML * NT);

    // 5. theta = pooled_n @ Wt + bt (fp16 -> fp32)
    {
        dim3 grid(NT / 128, MSML / 128);
        tgemm_kernel<<<grid, 256, TG_SMEM>>>(ppnhi, pwthi, bt, out, MSML, NT, Dc);
    }
}

// round 16
// speedup vs baseline: 1.1045x; 1.1045x over previous
#include <cuda_runtime.h>
#include <cuda_fp16.h>
#include <cstdint>

// Problem constants
#define Bc   4
#define Tc   2048
#define Dc   1024
#define Hc   16
#define DHc  64
#define T2c  1024
#define LN_EPS 1e-5f

#define MBIG (Bc * Tc)      // 8192
#define MSML (Bc * T2c)     // 4096
#define NT   (Dc / 2)       // 512

#define NCHK 128            // chunks per (b,h), 16 rows each

// ---------------- scratch (device globals) ----------------
// v is HEAD-MAJOR: [b][h][t][d]
__device__ __half g_vh[MBIG * Dc];        // 16 MB
__device__ float  g_wq[Hc * Dc];
__device__ float  g_w[Bc * Hc * Tc];      // w = exp(score) (no max; |s|<<1)
__device__ float  g_csumN[64 * NCHK * DHc];   // 2 MB chunk sums -> prefixes
__device__ float  g_csumZ[64 * NCHK];
__device__ float  g_cprefZ[64 * NCHK];
__device__ __half g_xhi[MBIG * Dc];       // 16 MB
__device__ __half g_wvhi[Dc * Dc];        // transposed [N][K]
__device__ __half g_wthi[NT * Dc];        // transposed [N][K]
__device__ __half g_pnhi[MSML * Dc];

// ---------------- 1. prep: wq + transpose/convert Wv, Wt --------------------
__global__ __launch_bounds__(256) void prep_kernel(
    const float* __restrict__ Wk, const float* __restrict__ q,
    const float* __restrict__ Wv, const float* __restrict__ Wt)
{
    __shared__ float tile[32][33];
    int bid = blockIdx.x, tid = threadIdx.x;
    if (bid < 64) {
        int idx = bid * 256 + tid;
        int d = idx >> 4, h = idx & 15;
        const float* wrow = Wk + (size_t)d * Dc + h * DHc;
        const float* qrow = q + h * DHc;
        float s = 0.f;
#pragma unroll
        for (int i = 0; i < DHc; i++) s = fmaf(wrow[i], qrow[i], s);
        g_wq[h * Dc + d] = s;
        return;
    }
    const float* W; __half* outT; int K, N, bx, by;
    if (bid < 64 + 1024) {
        int t = bid - 64;
        W = Wv; outT = g_wvhi; K = Dc; N = Dc; bx = t & 31; by = t >> 5;
    } else {
        int t = bid - 1088;
        W = Wt; outT = g_wthi; K = Dc; N = NT; bx = t & 15; by = t >> 4;
    }
    int tx = tid & 31, ty = tid >> 5;
    int bn = bx * 32, bk = by * 32;
#pragma unroll
    for (int j = 0; j < 4; j++)
        tile[ty + j * 8][tx] = W[(size_t)(bk + ty + j * 8) * N + bn + tx];
    __syncthreads();
#pragma unroll
    for (int j = 0; j < 4; j++) {
        int n = bn + ty + j * 8;
        int k = bk + tx;
        outT[(size_t)n * K + k] = __float2half_rn(tile[tx][ty + j * 8]);
    }
}

// ---------------- 2. scores (w = exp(s/8)) + x->fp16 ------------------------
__global__ __launch_bounds__(512) void scores_kernel(const float* __restrict__ x) {
    extern __shared__ float swq[];              // 16384 floats
    int tid = threadIdx.x;
    float4* swq4 = (float4*)swq;
    const float4* gwq4 = (const float4*)g_wq;
#pragma unroll
    for (int k = 0; k < 8; k++) swq4[tid + k * 512] = gwq4[tid + k * 512];

    int wid = tid >> 5, lane = tid & 31;
    int row = blockIdx.x * 16 + wid;
    const float4* xr4 = (const float4*)(x + (size_t)row * Dc);
    __half2* hp = (__half2*)(g_xhi + (size_t)row * Dc);
    float4 xv[8];
#pragma unroll
    for (int j = 0; j < 8; j++) {
        float4 v = xr4[lane + j * 32];
        xv[j] = v;
        hp[(lane + j * 32) * 2]     = __floats2half2_rn(v.x, v.y);
        hp[(lane + j * 32) * 2 + 1] = __floats2half2_rn(v.z, v.w);
    }
    __syncthreads();
    int b = row >> 11, t = row & (Tc - 1);
#pragma unroll
    for (int h = 0; h < 16; h++) {
        float s = 0.f;
#pragma unroll
        for (int j = 0; j < 8; j++) {
            float4 wv = swq4[h * 256 + lane + j * 32];
            s += xv[j].x * wv.x + xv[j].y * wv.y + xv[j].z * wv.z + xv[j].w * wv.w;
        }
#pragma unroll
        for (int o = 16; o; o >>= 1) s += __shfl_xor_sync(0xffffffffu, s, o);
        if (lane == 0) g_w[(b * Hc + h) * Tc + t] = expf(s * 0.125f);
    }
}

// ---------------- 3a. v-GEMM 128x256 (head-major) + fused 16-row chunk sums -
#define LD2 40
#define ASLAB (128 * LD2)               // halfs
#define BSLAB (256 * LD2)
#define STAGE (ASLAB + BSLAB)           // 15360 halfs
#define VG_SMEM (3 * STAGE * 2)         // 92160 B

__device__ __forceinline__ void mma16816(float* d, const uint32_t* a, const uint32_t* b) {
    asm volatile(
        "mma.sync.aligned.m16n8k16.row.col.f32.f16.f16.f32 "
        "{%0,%1,%2,%3}, {%4,%5,%6,%7}, {%8,%9}, {%0,%1,%2,%3};\n"
        : "+f"(d[0]), "+f"(d[1]), "+f"(d[2]), "+f"(d[3])
        : "r"(a[0]), "r"(a[1]), "r"(a[2]), "r"(a[3]), "r"(b[0]), "r"(b[1]));
}

__device__ __forceinline__ void cp_async16(uint32_t smem_addr, const void* gptr) {
    asm volatile("cp.async.cg.shared.global [%0], [%1], 16;\n"
                 :: "r"(smem_addr), "l"(gptr));
}

__global__ __launch_bounds__(256, 1) void vgemm_kernel(
    const __half* __restrict__ A, const __half* __restrict__ B,
    __half* __restrict__ C, int M, int N, int K)
{
    extern __shared__ __align__(16) __half smh[];
    int tid = threadIdx.x;
    int bm = blockIdx.y * 128, bn = blockIdx.x * 256;
    uint32_t sBase = (uint32_t)__cvta_generic_to_shared(smh);
    const int NS = K >> 5;

#define VLOAD_SLAB(slab, buf)                                                  \
    do {                                                                       \
        int k0_ = (slab) << 5;                                                 \
        uint32_t st_ = sBase + (uint32_t)(buf) * (STAGE * 2);                  \
        _Pragma("unroll")                                                      \
        for (int i_ = 0; i_ < 2; i_++) {                                       \
            int idx_ = tid + i_ * 256;                                         \
            int row_ = idx_ >> 2, part_ = idx_ & 3;                            \
            cp_async16(st_ + (uint32_t)((row_ * LD2 + part_ * 8) * 2),         \
                       A + (size_t)(bm + row_) * K + k0_ + part_ * 8);         \
        }                                                                      \
        _Pragma("unroll")                                                      \
        for (int i_ = 0; i_ < 4; i_++) {                                       \
            int idx_ = tid + i_ * 256;                                         \
            int row_ = idx_ >> 2, part_ = idx_ & 3;                            \
            cp_async16(st_ + (uint32_t)(ASLAB * 2 + (row_ * LD2 + part_ * 8) * 2), \
                       B + (size_t)(bn + row_) * K + k0_ + part_ * 8);         \
        }                                                                      \
        asm volatile("cp.async.commit_group;");                                \
    } while (0)

    int lane = tid & 31, wid = tid >> 5;
    int wm = wid & 1, wn = wid >> 1;
    int grp = lane >> 2, qid = lane & 3;

    float acc[4][8][4];
#pragma unroll
    for (int i = 0; i < 4; i++)
#pragma unroll
        for (int j = 0; j < 8; j++)
#pragma unroll
            for (int l = 0; l < 4; l++) acc[i][j][l] = 0.f;

    VLOAD_SLAB(0, 0);
    VLOAD_SLAB(1, 1);
    VLOAD_SLAB(2, 2);

    int buf = 0;
    for (int i = 0; i < NS; i++) {
        int rem = NS - 1 - i;
        if (rem >= 2)      asm volatile("cp.async.wait_group 2;");
        else if (rem == 1) asm volatile("cp.async.wait_group 1;");
        else               asm volatile("cp.async.wait_group 0;");
        __syncthreads();

        const __half* cA = smh + buf * STAGE;
        const __half* cB = smh + buf * STAGE + ASLAB;
#pragma unroll
        for (int ks = 0; ks < 2; ks++) {
            uint32_t ah[4][4], bh[8][2];
#pragma unroll
            for (int mt = 0; mt < 4; mt++) {
                int r = wm * 64 + mt * 16 + grp;
                ah[mt][0] = *(const uint32_t*)&cA[r * LD2 + ks * 16 + qid * 2];
                ah[mt][1] = *(const uint32_t*)&cA[(r + 8) * LD2 + ks * 16 + qid * 2];
                ah[mt][2] = *(const uint32_t*)&cA[r * LD2 + ks * 16 + qid * 2 + 8];
                ah[mt][3] = *(const uint32_t*)&cA[(r + 8) * LD2 + ks * 16 + qid * 2 + 8];
            }
#pragma unroll
            for (int nt = 0; nt < 8; nt++) {
                int n = wn * 64 + nt * 8 + grp;
                bh[nt][0] = *(const uint32_t*)&cB[n * LD2 + ks * 16 + qid * 2];
                bh[nt][1] = *(const uint32_t*)&cB[n * LD2 + ks * 16 + qid * 2 + 8];
            }
#pragma unroll
            for (int mt = 0; mt < 4; mt++)
#pragma unroll
                for (int nt = 0; nt < 8; nt++)
                    mma16816(acc[mt][nt], ah[mt], bh[nt]);
        }
        __syncthreads();
        if (i + 3 < NS) VLOAD_SLAB(i + 3, buf);
        buf = (buf == 2) ? 0 : buf + 1;
    }

    // store v (fp16, HEAD-MAJOR: [b][h][t][d])
    {
        int b = bm >> 11, tbase = bm & (Tc - 1);
        int h = (bn >> 6) + wn;
        __half* vbase = C + ((size_t)(b * Hc + h) * Tc + tbase) * DHc;
#pragma unroll
        for (int nt = 0; nt < 8; nt++) {
            int d = nt * 8 + qid * 2;
#pragma unroll
            for (int mt = 0; mt < 4; mt++) {
                int t = wm * 64 + mt * 16 + grp;
                *(__half2*)&vbase[(size_t)t * DHc + d] =
                    __floats2half2_rn(acc[mt][nt][0], acc[mt][nt][1]);
                *(__half2*)&vbase[(size_t)(t + 8) * DHc + d] =
                    __floats2half2_rn(acc[mt][nt][2], acc[mt][nt][3]);
            }
        }
    }

    // fused pass1: per-16-row-chunk sums of w*v (+ chunk Z) from fp32 accs
    __syncthreads();
    float* swe = (float*)smh;           // 512 floats, reuse smem
    int b = bm >> 11, tbase = bm & (Tc - 1);
#pragma unroll
    for (int i = 0; i < 2; i++) {
        int idx = tid + i * 256;
        int hh = idx >> 7, r = idx & 127;
        swe[idx] = g_w[(size_t)((b * Hc + (bn >> 6) + hh) * Tc) + tbase + r];
    }
    __syncthreads();
    {
        int bh = b * Hc + (bn >> 6) + wn;
        const float* swp = swe + wn * 128 + wm * 64;
        int cbase = (tbase >> 4) + wm * 4;
#pragma unroll
        for (int mt = 0; mt < 4; mt++) {
            float w0 = swp[mt * 16 + grp];
            float w8 = swp[mt * 16 + grp + 8];
            int c = cbase + mt;
            float z = w0 + w8;
#pragma unroll
            for (int o = 16; o >= 4; o >>= 1) z += __shfl_xor_sync(0xffffffffu, z, o);
            if (lane == 0) g_csumZ[bh * NCHK + c] = z;
#pragma unroll
            for (int nt = 0; nt < 8; nt++) {
                float s0 = w0 * acc[mt][nt][0] + w8 * acc[mt][nt][2];
                float s1 = w0 * acc[mt][nt][1] + w8 * acc[mt][nt][3];
#pragma unroll
                for (int o = 16; o >= 4; o >>= 1) {
                    s0 += __shfl_xor_sync(0xffffffffu, s0, o);
                    s1 += __shfl_xor_sync(0xffffffffu, s1, o);
                }
                if (grp == 0) {
                    int ix = (bh * NCHK + c) * DHc + nt * 8 + qid * 2;
                    g_csumN[ix] = s0;
                    g_csumN[ix + 1] = s1;
                }
            }
        }
    }
#undef VLOAD_SLAB
}

// ---------------- 3b. theta-GEMM: 128x128 tile, BK=32, 3-stage --------------
#define TSLAB (128 * LD2)
#define TSLAB_B (TSLAB * 2)
#define TG_SMEM (6 * TSLAB_B)           // 61440 B

__global__ __launch_bounds__(256, 1) void tgemm_kernel(
    const __half* __restrict__ A, const __half* __restrict__ B,
    const float* __restrict__ bias, float* __restrict__ C,
    int M, int N, int K)
{
    extern __shared__ __align__(16) __half smh[];
    __half* sA = smh;
    __half* sB = smh + 3 * TSLAB;
    int tid = threadIdx.x;
    int bm = blockIdx.y * 128, bn = blockIdx.x * 128;
    uint32_t aBase = (uint32_t)__cvta_generic_to_shared(sA);
    uint32_t bBase = (uint32_t)__cvta_generic_to_shared(sB);
    const int NS = K >> 5;

#define TLOAD_SLAB(slab, buf)                                                  \
    do {                                                                       \
        int k0_ = (slab) << 5;                                                 \
        _Pragma("unroll")                                                      \
        for (int i_ = 0; i_ < 2; i_++) {                                       \
            int idx_ = tid + i_ * 256;                                         \
            int row_ = idx_ >> 2, part_ = idx_ & 3;                            \
            uint32_t so_ = (uint32_t)((buf) * TSLAB_B + (row_ * LD2 + part_ * 8) * 2); \
            cp_async16(aBase + so_, A + (size_t)(bm + row_) * K + k0_ + part_ * 8);   \
            cp_async16(bBase + so_, B + (size_t)(bn + row_) * K + k0_ + part_ * 8);   \
        }                                                                      \
        asm volatile("cp.async.commit_group;");                                \
    } while (0)

    int lane = tid & 31, wid = tid >> 5;
    int wm = wid & 1, wn = wid >> 1;
    int grp = lane >> 2, qid = lane & 3;

    float acc[4][4][4];
#pragma unroll
    for (int i = 0; i < 4; i++)
#pragma unroll
        for (int j = 0; j < 4; j++)
#pragma unroll
            for (int l = 0; l < 4; l++) acc[i][j][l] = 0.f;

    TLOAD_SLAB(0, 0);
    if (NS > 1) TLOAD_SLAB(1, 1);
    if (NS > 2) TLOAD_SLAB(2, 2);

    int buf = 0;
    for (int i = 0; i < NS; i++) {
        int rem = NS - 1 - i;
        if (rem >= 2)      asm volatile("cp.async.wait_group 2;");
        else if (rem == 1) asm volatile("cp.async.wait_group 1;");
        else               asm volatile("cp.async.wait_group 0;");
        __syncthreads();

        const __half* cA = sA + buf * TSLAB;
        const __half* cB = sB + buf * TSLAB;
#pragma unroll
        for (int ks = 0; ks < 2; ks++) {
            uint32_t ah[4][4], bh[4][2];
#pragma unroll
            for (int mt = 0; mt < 4; mt++) {
                int r = wm * 64 + mt * 16 + grp;
                ah[mt][0] = *(const uint32_t*)&cA[r * LD2 + ks * 16 + qid * 2];
                ah[mt][1] = *(const uint32_t*)&cA[(r + 8) * LD2 + ks * 16 + qid * 2];
                ah[mt][2] = *(const uint32_t*)&cA[r * LD2 + ks * 16 + qid * 2 + 8];
                ah[mt][3] = *(const uint32_t*)&cA[(r + 8) * LD2 + ks * 16 + qid * 2 + 8];
            }
#pragma unroll
            for (int nt = 0; nt < 4; nt++) {
                int n = wn * 32 + nt * 8 + grp;
                bh[nt][0] = *(const uint32_t*)&cB[n * LD2 + ks * 16 + qid * 2];
                bh[nt][1] = *(const uint32_t*)&cB[n * LD2 + ks * 16 + qid * 2 + 8];
            }
#pragma unroll
            for (int mt = 0; mt < 4; mt++)
#pragma unroll
                for (int nt = 0; nt < 4; nt++)
                    mma16816(acc[mt][nt], ah[mt], bh[nt]);
        }
        __syncthreads();
        if (i + 3 < NS) TLOAD_SLAB(i + 3, buf);
        buf = (buf == 2) ? 0 : buf + 1;
    }

#pragma unroll
    for (int nt = 0; nt < 4; nt++) {
        int c0 = bn + wn * 32 + nt * 8 + qid * 2;
        float b0 = bias[c0], b1 = bias[c0 + 1];
#pragma unroll
        for (int mt = 0; mt < 4; mt++) {
            int r = bm + wm * 64 + mt * 16 + grp;
            *(float2*)&C[(size_t)r * N + c0] =
                make_float2(acc[mt][nt][0] + b0, acc[mt][nt][1] + b1);
            *(float2*)&C[(size_t)(r + 8) * N + c0] =
                make_float2(acc[mt][nt][2] + b0, acc[mt][nt][3] + b1);
        }
    }
#undef TLOAD_SLAB
}

// ---------------- 4. scan: exclusive prefix over chunk sums (once per bh) ---
__global__ __launch_bounds__(256) void scan_kernel() {
    __shared__ float sN[NCHK * DHc];      // 32 KB
    __shared__ float sZ[NCHK];
    int bh = blockIdx.x, tid = threadIdx.x;
    float4* s4 = (float4*)sN;
    float4* g4 = (float4*)(g_csumN + (size_t)bh * NCHK * DHc);
#pragma unroll
    for (int i = 0; i < 8; i++) s4[tid + i * 256] = g4[tid + i * 256];
    if (tid < NCHK) sZ[tid] = g_csumZ[bh * NCHK + tid];
    __syncthreads();
    if (tid < DHc) {
        float run = 0.f;
        for (int c = 0; c < NCHK; c++) {
            int ix = c * DHc + tid;
            float tv = sN[ix];
            sN[ix] = run;
            run += tv;
        }
    } else if (tid == DHc) {
        float rz = 0.f;
        for (int c = 0; c < NCHK; c++) {
            float tv = sZ[c];
            g_cprefZ[bh * NCHK + c] = rz;
            rz += tv;
        }
    }
    __syncthreads();
#pragma unroll
    for (int i = 0; i < 8; i++) g4[tid + i * 256] = s4[tid + i * 256];
}

// ---------------- 5. poolln: replay + LayerNorm + mag (fused, LN split) -----
// grid 512 = (b, jg): jg = 16-row chunk index (128 per b), 8 output rows each.
// block 512 (16 warps): warp h replays head h; then ALL 16 warps do LN:
// warp pair (2r, 2r+1) handles the two halves of output row r.
__global__ __launch_bounds__(512) void poolln_kernel(
    const float* __restrict__ lng, const float* __restrict__ lnb,
    const float* __restrict__ Wm, const float* __restrict__ bm,
    float* __restrict__ mag_out)
{
    __shared__ float sw[Hc * 16];           // 1 KB
    __shared__ float sPN[Hc * DHc];         // 4 KB prefix N
    __shared__ float sPZ[Hc];
    __shared__ __half sPool[8 * Dc];        // 16 KB pooled tile [j_local][d]
    __shared__ float2 sRed[16];             // per-warp (sum, sumsq)
    __shared__ float sDot[16];              // per-warp mag partials
    int blk = blockIdx.x;
    int b = blk >> 7, jg = blk & 127;
    int tid = threadIdx.x, wid = tid >> 5, lane = tid & 31;
    int t0 = jg * 16;

    if (tid < Hc * 16) {
        int h = tid >> 4, i = tid & 15;
        sw[tid] = g_w[(b * Hc + h) * Tc + t0 + i];
    }
#pragma unroll
    for (int k = 0; k < 2; k++) {
        int s = tid + k * 512;              // s = h*64 + d
        int h = s >> 6, d = s & 63;
        sPN[s] = g_csumN[((size_t)(b * Hc + h) * NCHK + jg) * DHc + d];
    }
    if (tid < Hc) sPZ[tid] = g_cprefZ[(b * Hc + tid) * NCHK + jg];
    __syncthreads();

    // replay: warp = head; contiguous 2 KB v stream
    {
        int h = wid;
        const __half2* vp = (const __half2*)(g_vh +
            ((size_t)(b * Hc + h) * Tc + t0) * DHc) + lane;
        float2 accN = make_float2(sPN[h * 64 + 2 * lane], sPN[h * 64 + 2 * lane + 1]);
        float accZ = sPZ[h];
        __half2* pool = (__half2*)sPool + h * 32 + lane;   // row stride 512 half2
#pragma unroll
        for (int i = 0; i < 16; i += 2) {
            float w0 = sw[h * 16 + i];
            float2 f0 = __half22float2(vp[i * 32]);
            accN.x = fmaf(w0, f0.x, accN.x);
            accN.y = fmaf(w0, f0.y, accN.y);
            accZ += w0;
            float inv = __fdividef(1.f, accZ);
            pool[(i >> 1) * 512] = __floats2half2_rn(accN.x * inv, accN.y * inv);
            float w1 = sw[h * 16 + i + 1];
            float2 f1 = __half22float2(vp[(i + 1) * 32]);
            accN.x = fmaf(w1, f1.x, accN.x);
            accN.y = fmaf(w1, f1.y, accN.y);
            accZ += w1;
        }
    }
    __syncthreads();

    // LN + mag: all 16 warps; warp pair (2r, 2r+1) = halves of row r.
    int r = wid >> 1, hf = wid & 1;
    const __half2* row = (const __half2*)sPool + r * 512 + hf * 256 + lane;
    float2 vals[8];
    float s = 0.f, sq = 0.f;
#pragma unroll
    for (int k = 0; k < 8; k++) {
        float2 v = __half22float2(row[k * 32]);
        vals[k] = v;
        s += v.x + v.y;
        sq += v.x * v.x + v.y * v.y;
    }
#pragma unroll
    for (int o = 16; o; o >>= 1) {
        s += __shfl_xor_sync(0xffffffffu, s, o);
        sq += __shfl_xor_sync(0xffffffffu, sq, o);
    }
    if (lane == 0) sRed[wid] = make_float2(s, sq);
    __syncthreads();
    float2 pa = sRed[r * 2], pb = sRed[r * 2 + 1];
    float mu = (pa.x + pb.x) * (1.f / Dc);
    float var = (pa.y + pb.y) * (1.f / Dc) - mu * mu;
    float rstd = rsqrtf(var + LN_EPS);

    int rowidx = b * T2c + jg * 8 + r;
    __half2* hp = (__half2*)(g_pnhi + (size_t)rowidx * Dc);
    float dot = 0.f;
#pragma unroll
    for (int k = 0; k < 8; k++) {
        int d2 = hf * 256 + lane + k * 32;
        float2 g2 = ((const float2*)lng)[d2];
        float2 b2 = ((const float2*)lnb)[d2];
        float yx = (vals[k].x - mu) * rstd * g2.x + b2.x;
        float yy = (vals[k].y - mu) * rstd * g2.y + b2.y;
        hp[d2] = __floats2half2_rn(yx, yy);
        float2 wm2 = ((const float2*)Wm)[d2];
        dot += yx * wm2.x + yy * wm2.y;
    }
#pragma unroll
    for (int o = 16; o; o >>= 1) dot += __shfl_xor_sync(0xffffffffu, dot, o);
    if (lane == 0) sDot[wid] = dot;
    __syncthreads();
    if (hf == 0 && lane == 0) {
        float dtot = sDot[r * 2] + sDot[r * 2 + 1];
        mag_out[rowidx] = 1.f / (1.f + expf(-(dtot + bm[0])));
    }
}

// ---------------- launch ----------------
extern "C" void kernel_launch(void* const* d_in, const int* in_sizes, int n_in,
                              void* d_out, int out_size) {
    const float* x   = (const float*)d_in[0];
    const float* qy  = (const float*)d_in[1];
    const float* Wk  = (const float*)d_in[2];
    const float* Wv  = (const float*)d_in[3];
    const float* Wt  = (const float*)d_in[4];
    const float* bt  = (const float*)d_in[5];
    const float* Wm  = (const float*)d_in[6];
    const float* bm  = (const float*)d_in[7];
    const float* lng = (const float*)d_in[8];
    const float* lnb = (const float*)d_in[9];
    float* out = (float*)d_out;

    __half *pvh, *pxhi, *pwvhi, *pwthi, *ppnhi;
    cudaGetSymbolAddress((void**)&pvh, g_vh);
    cudaGetSymbolAddress((void**)&pxhi, g_xhi);
    cudaGetSymbolAddress((void**)&pwvhi, g_wvhi);
    cudaGetSymbolAddress((void**)&pwthi, g_wthi);
    cudaGetSymbolAddress((void**)&ppnhi, g_pnhi);

    cudaFuncSetAttribute(scores_kernel,
                         cudaFuncAttributeMaxDynamicSharedMemorySize, 65536);
    cudaFuncSetAttribute(vgemm_kernel,
                         cudaFuncAttributeMaxDynamicSharedMemorySize, VG_SMEM);
    cudaFuncSetAttribute(tgemm_kernel,
                         cudaFuncAttributeMaxDynamicSharedMemorySize, TG_SMEM);

    // 1. weight prep (wq + WvT + WtT)
    prep_kernel<<<1600, 256>>>(Wk, qy, Wv, Wt);

    // 2. w = exp(scores), x -> fp16
    scores_kernel<<<MBIG / 16, 512, 65536>>>(x);

    // 3. v = x @ Wv (fp16, head-major) + fused 16-row chunk sums
    {
        dim3 grid(Dc / 256, MBIG / 128);
        vgemm_kernel<<<grid, 256, VG_SMEM>>>(pxhi, pwvhi, pvh, MBIG, Dc, Dc);
    }

    // 4. scan chunk sums (once per bh)
    scan_kernel<<<64, 256>>>();

    // 5. poolln: replay + LN + mag -> pnhi + mag (fused)
    poolln_kernel<<<512, 512>>>(lng, lnb, Wm, bm, out + (size_t)MSML * NT);

    // 6. theta = pooled_n @ Wt + bt (fp16 -> fp32)
    {
        dim3 grid(NT / 128, MSML / 128);
        tgemm_kernel<<<grid, 256, TG_SMEM>>>(ppnhi, pwthi, bt, out, MSML, NT, Dc);
    }
}